// round 2
// baseline (speedup 1.0000x reference)
#include <cuda_runtime.h>
#include <stdint.h>

// Problem constants (fixed by the reference problem definition)
#define FEAT_DIM 128
#define BATCH    4
#define NY       512
#define NX       512
#define NPIX     (BATCH * NY * NX)   // 1,048,576

#define XT   64        // x-tile per block
#define CCH  64        // channels per smem chunk (2 chunks cover FEAT_DIM)
#define CP   65        // padded stride (floats): bank = xl + lane -> conflict-free

// 4 MB scratch: winner map. INVARIANT: all-zero on entry to kernel_launch.
//  - zero at module load (device globals are zero-initialized)
//  - k_argmax writes (voxel_index + 1) via atomicMax (last-write-wins == max index)
//  - k_gather restores every nonzero entry it consumes back to 0
// => no init kernel needed, identical work every call.
__device__ int g_map[NPIX];

// ---------------------------------------------------------------------------
// Kernel 1: winner per pixel.  coors: [N,4] int32 (b, z, y, x)
// ---------------------------------------------------------------------------
__global__ void k_argmax_map(const int* __restrict__ coors, int n) {
    int i = blockIdx.x * blockDim.x + threadIdx.x;
    if (i >= n) return;
    int4 c = reinterpret_cast<const int4*>(coors)[i];  // b, z, y, x
    int flat = c.x * (NY * NX) + c.z * NX + c.w;
    atomicMax(&g_map[flat], i + 1);
}

// ---------------------------------------------------------------------------
// Kernel 2: gather + transpose. One block per (b, y, 64-x tile).
// Two channel-chunks of 64 keep smem at ~17KB -> 8 blocks/SM (64 warps, 100%).
// Writes the FULL output (zeros for empty pixels) in coalesced order.
// ---------------------------------------------------------------------------
__global__ __launch_bounds__(256)
void k_gather(const float* __restrict__ feat, float* __restrict__ out) {
    __shared__ float tile[XT * CP];   // [x][c-chunk], padded
    __shared__ int   vidx[XT];

    int blk = blockIdx.x;              // 0 .. BATCH*NY*(NX/XT)-1
    int xt  = blk & (NX / XT - 1);     // 0..7
    int y   = (blk >> 3) & (NY - 1);   // 0..511
    int b   = blk >> 12;               // 0..3
    int x0  = xt * XT;

    int t = threadIdx.x, warp = t >> 5, lane = t & 31;

    if (t < XT) {
        int idx = b * (NY * NX) + y * NX + x0 + t;
        int v = g_map[idx];
        vidx[t] = v - 1;               // -1 if empty
        if (v) g_map[idx] = 0;         // restore invariant for next call
    }
    __syncthreads();

    #pragma unroll
    for (int ch = 0; ch < FEAT_DIM / CCH; ch++) {
        int cbase = ch * CCH;

        // Fill: one warp per x (8 x's/warp); coalesced 128B gmem reads,
        // smem bank = xl + lane -> conflict-free.
        #pragma unroll
        for (int k = 0; k < XT / 8; k++) {
            int xl = k * 8 + warp;
            int v  = vidx[xl];
            if (v >= 0) {
                const float* row = feat + (size_t)v * FEAT_DIM + cbase;
                tile[xl * CP + lane]      = row[lane];
                tile[xl * CP + 32 + lane] = row[32 + lane];
            } else {
                tile[xl * CP + lane]      = 0.0f;
                tile[xl * CP + 32 + lane] = 0.0f;
            }
        }
        __syncthreads();

        // Drain: 64 channels x 64 x's. Each warp-row writes 32 contiguous x's
        // for one channel: 128B coalesced STG; smem bank = (xh+lane) + c ->
        // conflict-free. Fully unrolled: 16 independent LDS+STG pairs (MLP).
        size_t obase = (((size_t)b * FEAT_DIM + cbase) * NY + y) * NX + x0;
        #pragma unroll
        for (int r = 0; r < (CCH * 2) / 8; r++) {
            int rr = r * 8 + warp;         // 0..127
            int c  = rr >> 1;
            int xh = (rr & 1) << 5;
            out[obase + (size_t)c * (NY * NX) + xh + lane] =
                tile[(xh + lane) * CP + c];
        }
        __syncthreads();
    }
}

// ---------------------------------------------------------------------------
extern "C" void kernel_launch(void* const* d_in, const int* in_sizes, int n_in,
                              void* d_out, int out_size) {
    const float* feat  = (const float*)d_in[0];
    const int*   coors = (const int*)d_in[1];
    float*       out   = (float*)d_out;

    int n = in_sizes[0] / FEAT_DIM;   // number of voxels

    // 1) winner per pixel (map is all-zero by invariant)
    k_argmax_map<<<(n + 255) / 256, 256>>>(coors, n);
    // 2) gather + transpose full output (and restore map to zero)
    k_gather<<<BATCH * NY * (NX / XT), 256>>>(feat, out);
}

// round 3
// speedup vs baseline: 1.2614x; 1.2614x over previous
#include <cuda_runtime.h>
#include <stdint.h>

// Problem constants (fixed by the reference problem definition)
#define FEAT_DIM 128
#define BATCH    4
#define NY       512
#define NX       512
#define NPIX     (BATCH * NY * NX)   // 1,048,576

#define XT  64         // x-tile per block
#define CP  129        // padded stride (odd) -> conflict-free both smem phases
#define NTH 512        // 16 warps/block -> 4 blocks/SM = 64 warps = 100% occ

// 4 MB scratch: winner map. INVARIANT: all-zero on entry to kernel_launch.
//  - zero at module load (device globals are zero-initialized)
//  - k_argmax writes (voxel_index + 1) via atomicMax (last-write-wins == max idx)
//  - k_gather restores every entry it consumed back to 0
// => no init kernel, identical work every call (graph-replay safe).
__device__ int g_map[NPIX];

// ---------------------------------------------------------------------------
// Kernel 1: winner per pixel.  coors: [N,4] int32 (b, z, y, x)
// ---------------------------------------------------------------------------
__global__ void k_argmax_map(const int* __restrict__ coors, int n) {
    int i = blockIdx.x * blockDim.x + threadIdx.x;
    if (i >= n) return;
    int4 c = reinterpret_cast<const int4*>(coors)[i];  // b, z, y, x
    int flat = c.x * (NY * NX) + c.z * NX + c.w;
    atomicMax(&g_map[flat], i + 1);
}

// ---------------------------------------------------------------------------
// Kernel 2: gather + transpose. One block per (b, y, 64-x tile).
// Single fill->drain pass (2 barriers), 512 threads, 33KB smem.
// Writes the FULL output (zeros for empty pixels) in coalesced order.
// ---------------------------------------------------------------------------
__global__ __launch_bounds__(NTH)
void k_gather(const float* __restrict__ feat, float* __restrict__ out) {
    __shared__ float tile[XT * CP];   // [x][c], padded (CP odd)
    __shared__ int   vidx[XT];

    int blk = blockIdx.x;              // 0 .. BATCH*NY*(NX/XT)-1
    int xt  = blk & (NX / XT - 1);     // 0..7
    int y   = (blk >> 3) & (NY - 1);   // 0..511
    int b   = blk >> 12;               // 0..3
    int x0  = xt * XT;

    int t = threadIdx.x, warp = t >> 5, lane = t & 31;

    if (t < XT) {
        int idx = b * (NY * NX) + y * NX + x0 + t;
        int v = g_map[idx];
        vidx[t] = v - 1;               // -1 if empty
        if (v) g_map[idx] = 0;         // restore all-zero invariant
    }
    __syncthreads();

    // Fill: 16 warps cover 64 x's (4 each); per x, 4 coalesced 128B LDG of the
    // 512B feat row. smem bank = xl + lane (CP odd) -> conflict-free.
    #pragma unroll
    for (int k = 0; k < XT / 16; k++) {
        int xl = k * 16 + warp;
        int v  = vidx[xl];
        float* dst = &tile[xl * CP];
        if (v >= 0) {
            const float* row = feat + (size_t)v * FEAT_DIM;
            #pragma unroll
            for (int it = 0; it < 4; it++)
                dst[it * 32 + lane] = row[it * 32 + lane];
        } else {
            #pragma unroll
            for (int it = 0; it < 4; it++)
                dst[it * 32 + lane] = 0.0f;
        }
    }
    __syncthreads();

    // Drain: 128 channels x 64 x's = 256 (c, x-half) rows / 16 warps = 16 each.
    // Each row: conflict-free LDS (bank = xh+lane+c) + 128B coalesced STG.
    // Fully unrolled -> 16 independent LDS/STG pairs in flight.
    size_t obase = (((size_t)b * FEAT_DIM) * NY + y) * NX + x0;
    #pragma unroll
    for (int r = 0; r < (FEAT_DIM * 2) / 16; r++) {
        int rr = r * 16 + warp;            // 0..255
        int c  = rr >> 1;
        int xh = (rr & 1) << 5;
        out[obase + (size_t)c * (NY * NX) + xh + lane] =
            tile[(xh + lane) * CP + c];
    }
}

// ---------------------------------------------------------------------------
extern "C" void kernel_launch(void* const* d_in, const int* in_sizes, int n_in,
                              void* d_out, int out_size) {
    const float* feat  = (const float*)d_in[0];
    const int*   coors = (const int*)d_in[1];
    float*       out   = (float*)d_out;

    int n = in_sizes[0] / FEAT_DIM;   // number of voxels

    // 1) winner per pixel (map is all-zero by invariant)
    k_argmax_map<<<(n + 255) / 256, 256>>>(coors, n);
    // 2) gather + transpose full output (and restore map to zero)
    k_gather<<<BATCH * NY * (NX / XT), NTH>>>(feat, out);
}